// round 9
// baseline (speedup 1.0000x reference)
#include <cuda_runtime.h>
#include <cuda_bf16.h>
#include <math.h>

// Problem constants
#define CB 8
#define CN 1024
#define CD 512
#define CO 512
#define CH 8
#define CHD 64
#define QKVLD 1536   // 3*O
#define MROWS (CB*CN) // 8192

// ---------------- scratch (static device allocations; no cudaMalloc) ----------
__device__ float g_fmask[MROWS];
__device__ __nv_bfloat16 g_xh[MROWS*CD],  g_xl[MROWS*CD];
__device__ __nv_bfloat16 g_qwh[QKVLD*CD], g_qwl[QKVLD*CD];
__device__ __nv_bfloat16 g_w1h[CO*CO], g_w1l[CO*CO];
__device__ __nv_bfloat16 g_w2h[CO*CO], g_w2l[CO*CO];
__device__ __nv_bfloat16 g_wrh[CO*CD], g_wrl[CO*CD];
__device__ __nv_bfloat16 g_qh[(size_t)MROWS*QKVLD], g_ql[(size_t)MROWS*QKVLD];
__device__ __nv_bfloat16 g_Hh[MROWS*CO], g_Hl[MROWS*CO];
__device__ __nv_bfloat16 g_Th[MROWS*CO], g_Tl[MROWS*CO];

// ---------------------------------------------------------------------------
__device__ __forceinline__ void bsplit(float v, __nv_bfloat16& h, __nv_bfloat16& l){
    h = __float2bfloat16(v);
    l = __float2bfloat16(v - __bfloat162float(h));
}
__device__ __forceinline__ unsigned packbf(__nv_bfloat16 e, __nv_bfloat16 o){
    return ((unsigned)__bfloat16_as_ushort(o) << 16) | (unsigned)__bfloat16_as_ushort(e);
}
__device__ __forceinline__ void mma16816(float* c, const unsigned* a, const unsigned* b){
    asm volatile("mma.sync.aligned.m16n8k16.row.col.f32.bf16.bf16.f32 "
        "{%0,%1,%2,%3}, {%4,%5,%6,%7}, {%8,%9}, {%0,%1,%2,%3};"
        : "+f"(c[0]), "+f"(c[1]), "+f"(c[2]), "+f"(c[3])
        : "r"(a[0]), "r"(a[1]), "r"(a[2]), "r"(a[3]), "r"(b[0]), "r"(b[1]));
}
__device__ __forceinline__ void ldsm4(unsigned* r, const void* p){
    unsigned a = (unsigned)__cvta_generic_to_shared(p);
    asm volatile("ldmatrix.sync.aligned.m8n8.x4.shared.b16 {%0,%1,%2,%3}, [%4];"
        : "=r"(r[0]), "=r"(r[1]), "=r"(r[2]), "=r"(r[3]) : "r"(a));
}
__device__ __forceinline__ void ldsm4t(unsigned* r, const void* p){
    unsigned a = (unsigned)__cvta_generic_to_shared(p);
    asm volatile("ldmatrix.sync.aligned.m8n8.x4.trans.shared.b16 {%0,%1,%2,%3}, [%4];"
        : "=r"(r[0]), "=r"(r[1]), "=r"(r[2]), "=r"(r[3]) : "r"(a));
}
__device__ __forceinline__ void ldsm2(unsigned* r, const void* p){
    unsigned a = (unsigned)__cvta_generic_to_shared(p);
    asm volatile("ldmatrix.sync.aligned.m8n8.x2.shared.b16 {%0,%1}, [%2];"
        : "=r"(r[0]), "=r"(r[1]) : "r"(a));
}
__device__ __forceinline__ void cpa16(void* dst_smem, const void* src){
    unsigned sa = (unsigned)__cvta_generic_to_shared(dst_smem);
    asm volatile("cp.async.cg.shared.global [%0], [%1], 16;" :: "r"(sa), "l"(src));
}
#define CPA_COMMIT asm volatile("cp.async.commit_group;")
#define CPA_WAIT0  asm volatile("cp.async.wait_group 0;")

// ---------------------------------------------------------------------------
// Mask conversion (dtype auto-detect; bench data treated strictly as data)
// ---------------------------------------------------------------------------
__global__ void mask_convert(const unsigned char* __restrict__ raw,
                             float* __restrict__ fmask)
{
    __shared__ int s_m1, s_m23, s_gt1;
    int t = threadIdx.x;
    if (t == 0) { s_m1 = 0; s_m23 = 0; s_gt1 = 0; }
    __syncthreads();
    int m1 = 0, m23 = 0, g = 0;
    for (int i = t; i < MROWS; i += 256) {
        unsigned char v = raw[i];
        if (v) {
            int p = i & 3;
            if (p == 1) m1 = 1;
            if (p >= 2) m23 = 1;
            if (v > 1) g = 1;
        }
    }
    if (m1)  atomicOr(&s_m1, 1);
    if (m23) atomicOr(&s_m23, 1);
    if (g)   atomicOr(&s_gt1, 1);
    __syncthreads();
    int mis = s_m1 | s_m23;
    int mode;
    if (!mis)            mode = 0;
    else if (!s_gt1)     mode = 1;
    else if (s_m1)       mode = 3;
    else                 mode = 2;
    for (int i = t; i < MROWS; i += 256) {
        float f;
        if (mode == 0)      f = (((const int*)raw)[i]            != 0)   ? 1.f : 0.f;
        else if (mode == 1) f = (raw[i]                          != 0)   ? 1.f : 0.f;
        else if (mode == 2) f = (((const float*)raw)[i]          != 0.f) ? 1.f : 0.f;
        else                f = (((const unsigned short*)raw)[i] != 0)   ? 1.f : 0.f;
        fmask[i] = f;
    }
}

// ---------------------------------------------------------------------------
// Fused splitter: x, qkv_w, w1, w2, wr in one launch.
// ---------------------------------------------------------------------------
#define SPL0 (MROWS*CD)
#define SPL1 (QKVLD*CD)
#define SPL2 (CO*CO)
#define SPL3 (CO*CO)
#define SPL4 (CO*CD)
#define SPLT (SPL0+SPL1+SPL2+SPL3+SPL4)
__global__ void split5(
    const float* __restrict__ s0, const float* __restrict__ s1,
    const float* __restrict__ s2, const float* __restrict__ s3,
    const float* __restrict__ s4,
    __nv_bfloat16* __restrict__ h0, __nv_bfloat16* __restrict__ l0,
    __nv_bfloat16* __restrict__ h1, __nv_bfloat16* __restrict__ l1,
    __nv_bfloat16* __restrict__ h2, __nv_bfloat16* __restrict__ l2,
    __nv_bfloat16* __restrict__ h3, __nv_bfloat16* __restrict__ l3,
    __nv_bfloat16* __restrict__ h4, __nv_bfloat16* __restrict__ l4)
{
    int i = blockIdx.x * 256 + threadIdx.x;
    if (i >= SPLT) return;
    const float* s; __nv_bfloat16 *h, *l; int j = i;
    if (j < SPL0)                { s = s0; h = h0; l = l0; }
    else if ((j -= SPL0) < SPL1) { s = s1; h = h1; l = l1; }
    else if ((j -= SPL1) < SPL2) { s = s2; h = h2; l = l2; }
    else if ((j -= SPL2) < SPL3) { s = s3; h = h3; l = l3; }
    else { j -= SPL3;              s = s4; h = h4; l = l4; }
    __nv_bfloat16 hh, ll;
    bsplit(s[j], hh, ll);
    h[j] = hh; l[j] = ll;
}

// ---------------------------------------------------------------------------
// Tensor-core NT GEMM (bf16x3), cp.async double-buffered, ldmatrix fragments.
// 128x128, BK=16, 256 thr (8 warps = 2m x 4n).
// EPI: 0 split-store; 1 relu+split-store; 2 Cf=0.5v; 3 Cf+=0.5*fmask[m]*v
// ---------------------------------------------------------------------------
template<int EPI>
__global__ __launch_bounds__(256) void gemm_tc(
    const __nv_bfloat16* __restrict__ Ahg, const __nv_bfloat16* __restrict__ Alg,
    const __nv_bfloat16* __restrict__ Whg, const __nv_bfloat16* __restrict__ Wlg,
    const float* __restrict__ bias, const float* __restrict__ fmask,
    float* __restrict__ Cf, __nv_bfloat16* __restrict__ Ch, __nv_bfloat16* __restrict__ Cl,
    int K, int lda, int ldw, int ldc)
{
    __shared__ unsigned Ah[2][128*12], Al[2][128*12], Wh[2][128*12], Wl[2][128*12];
    const int tid = threadIdx.x;
    const int lane = tid & 31, wid = tid >> 5;
    const int wm = wid & 1, wn = wid >> 1;
    const int row0 = blockIdx.y * 128, col0 = blockIdx.x * 128;
    const int lr = tid >> 1, lh = tid & 1;
    const int qr = lane >> 2, qk = lane & 3;

    const int arow  = wm*64 + (lane & 7) + ((lane >> 3) & 1) * 8;
    const int aword = ((lane >> 4) & 1) * 4;
    const int brow  = wn*32 + (lane & 7);
    const int bword = ((lane >> 3) & 1) * 4;

    float acc[4][4][4];
    #pragma unroll
    for (int mt = 0; mt < 4; mt++)
        #pragma unroll
        for (int nt = 0; nt < 4; nt++)
            #pragma unroll
            for (int i = 0; i < 4; i++) acc[mt][nt][i] = 0.f;

    {
        size_t aoff = (size_t)(row0 + lr) * lda + lh * 8;
        size_t woff = (size_t)(col0 + lr) * ldw + lh * 8;
        cpa16(&Ah[0][lr*12 + lh*4], Ahg + aoff);
        cpa16(&Al[0][lr*12 + lh*4], Alg + aoff);
        cpa16(&Wh[0][lr*12 + lh*4], Whg + woff);
        cpa16(&Wl[0][lr*12 + lh*4], Wlg + woff);
    }
    CPA_COMMIT;

    int st = 0;
    for (int k0 = 0; k0 < K; k0 += 16, st ^= 1) {
        CPA_WAIT0;
        __syncthreads();
        if (k0 + 16 < K) {
            size_t aoff = (size_t)(row0 + lr) * lda + k0 + 16 + lh * 8;
            size_t woff = (size_t)(col0 + lr) * ldw + k0 + 16 + lh * 8;
            cpa16(&Ah[st^1][lr*12 + lh*4], Ahg + aoff);
            cpa16(&Al[st^1][lr*12 + lh*4], Alg + aoff);
            cpa16(&Wh[st^1][lr*12 + lh*4], Whg + woff);
            cpa16(&Wl[st^1][lr*12 + lh*4], Wlg + woff);
        }
        CPA_COMMIT;

        const unsigned* sAh = Ah[st]; const unsigned* sAl = Al[st];
        const unsigned* sWh = Wh[st]; const unsigned* sWl = Wl[st];
        unsigned afh[4][4], afl[4][4], bfh[4][2], bfl[4][2];
        #pragma unroll
        for (int mt = 0; mt < 4; mt++) {
            ldsm4(afh[mt], &sAh[(arow + mt*16)*12 + aword]);
            ldsm4(afl[mt], &sAl[(arow + mt*16)*12 + aword]);
        }
        #pragma unroll
        for (int nt = 0; nt < 4; nt++) {
            ldsm2(bfh[nt], &sWh[(brow + nt*8)*12 + bword]);
            ldsm2(bfl[nt], &sWl[(brow + nt*8)*12 + bword]);
        }
        #pragma unroll
        for (int mt = 0; mt < 4; mt++)
            #pragma unroll
            for (int nt = 0; nt < 4; nt++) {
                mma16816(acc[mt][nt], afh[mt], bfh[nt]);
                mma16816(acc[mt][nt], afh[mt], bfl[nt]);
                mma16816(acc[mt][nt], afl[mt], bfh[nt]);
            }
    }

    #pragma unroll
    for (int mt = 0; mt < 4; mt++)
        #pragma unroll
        for (int nt = 0; nt < 4; nt++) {
            const float* a = acc[mt][nt];
            int rbase = row0 + wm*64 + mt*16 + qr;
            int cbase = col0 + wn*32 + nt*8 + qk*2;
            float bv0 = bias[cbase], bv1 = bias[cbase + 1];
            #pragma unroll
            for (int hf = 0; hf < 2; hf++) {
                int r = rbase + hf*8;
                float v0 = a[hf*2+0] + bv0;
                float v1 = a[hf*2+1] + bv1;
                size_t idx = (size_t)r * ldc + cbase;
                if constexpr (EPI == 0 || EPI == 1) {
                    if constexpr (EPI == 1) { v0 = fmaxf(v0, 0.f); v1 = fmaxf(v1, 0.f); }
                    __nv_bfloat16 h0,l0,h1,l1;
                    bsplit(v0, h0, l0); bsplit(v1, h1, l1);
                    __nv_bfloat162 ph; ph.x = h0; ph.y = h1;
                    __nv_bfloat162 pl; pl.x = l0; pl.y = l1;
                    *(__nv_bfloat162*)(Ch + idx) = ph;
                    *(__nv_bfloat162*)(Cl + idx) = pl;
                } else if constexpr (EPI == 2) {
                    float2 o; o.x = 0.5f*v0; o.y = 0.5f*v1;
                    *(float2*)(Cf + idx) = o;
                } else {
                    float fm = 0.5f * fmask[r];
                    float2 cur = *(float2*)(Cf + idx);
                    cur.x += fm*v0; cur.y += fm*v1;
                    *(float2*)(Cf + idx) = cur;
                }
            }
        }
}

// ---------------------------------------------------------------------------
// Flash-fused attention (bf16x3, online softmax, P register-resident).
// V stored row-major [seq][64] like K; P-V B fragments via ldmatrix.x4.trans.
// cp.async double-buffered K+V tiles (2 stages x 4 arrays x 18KB = 144KB smem).
// Grid: (CN/128, B*H). 256 thr = 8 warps x 16 Q rows.
// ---------------------------------------------------------------------------
#define KS_STRIDE 36
#define KS_WORDS (128*KS_STRIDE)                 // 4608 u32 per array
#define FL_SMEM_BYTES (8*KS_WORDS*4)             // 147456

__global__ void __launch_bounds__(256, 1) flash_tc(
    const __nv_bfloat16* __restrict__ qh, const __nv_bfloat16* __restrict__ ql,
    const float* __restrict__ slw, const float* __restrict__ fmask,
    __nv_bfloat16* __restrict__ Hh, __nv_bfloat16* __restrict__ Hl)
{
    extern __shared__ unsigned smem[];
    unsigned* KshS[2] = { smem,            smem + KS_WORDS };
    unsigned* KslS[2] = { smem + 2*KS_WORDS, smem + 3*KS_WORDS };
    unsigned* VshS[2] = { smem + 4*KS_WORDS, smem + 5*KS_WORDS };
    unsigned* VslS[2] = { smem + 6*KS_WORDS, smem + 7*KS_WORDS };

    const int z = blockIdx.y, b = z >> 3, h = z & 7;
    const int qt = blockIdx.x;
    const int tid = threadIdx.x;
    const int lane = tid & 31, wid = tid >> 5;
    const int qr = lane >> 2, qk = lane & 3;

    const size_t bhq = (size_t)b*CN*QKVLD + h*CHD;
    const size_t bhk = bhq + CO;
    const size_t bhv = bhq + 2*CO;

    const int lrow = tid >> 1, lq = tid & 1;                // tile row loader
    const int krow  = ((lane >> 4) & 1) * 8 + (lane & 7);   // K ldsm row (+ntp*16)
    const int kword = ((lane >> 3) & 1) * 4;
    const int vrow  = lane & 15;                            // V ldsm.trans row (+kk*16)
    const int vword = (lane >> 4) * 4;                      // n 8-elem group

    // ---- stage Q tile through K stage-0 buffer, pull fragments ----
    {
        size_t qoff = bhq + (size_t)(qt*128 + lrow)*QKVLD + lq*32;
        #pragma unroll
        for (int i = 0; i < 4; i++) {
            *(uint4*)&KshS[0][lrow*KS_STRIDE + lq*16 + i*4] = *(const uint4*)(qh + qoff + i*8);
            *(uint4*)&KslS[0][lrow*KS_STRIDE + lq*16 + i*4] = *(const uint4*)(ql + qoff + i*8);
        }
    }
    __syncthreads();
    unsigned qfh[4][4], qfl[4][4];
    #pragma unroll
    for (int kw = 0; kw < 4; kw++) {
        int r0 = (wid*16 + qr) * KS_STRIDE + kw*8;
        int r8 = (wid*16 + qr + 8) * KS_STRIDE + kw*8;
        qfh[kw][0] = KshS[0][r0 + qk];     qfh[kw][1] = KshS[0][r8 + qk];
        qfh[kw][2] = KshS[0][r0 + qk + 4]; qfh[kw][3] = KshS[0][r8 + qk + 4];
        qfl[kw][0] = KslS[0][r0 + qk];     qfl[kw][1] = KslS[0][r8 + qk];
        qfl[kw][2] = KslS[0][r0 + qk + 4]; qfl[kw][3] = KslS[0][r8 + qk + 4];
    }
    __syncthreads();

    // ---- prologue: stage K/V tile 0 via cp.async ----
    {
        size_t koff = bhk + (size_t)lrow*QKVLD + lq*32;
        size_t voff = bhv + (size_t)lrow*QKVLD + lq*32;
        #pragma unroll
        for (int i = 0; i < 4; i++) {
            cpa16(&KshS[0][lrow*KS_STRIDE + lq*16 + i*4], qh + koff + i*8);
            cpa16(&KslS[0][lrow*KS_STRIDE + lq*16 + i*4], ql + koff + i*8);
            cpa16(&VshS[0][lrow*KS_STRIDE + lq*16 + i*4], qh + voff + i*8);
            cpa16(&VslS[0][lrow*KS_STRIDE + lq*16 + i*4], ql + voff + i*8);
        }
    }
    CPA_COMMIT;

    const float wd = slw[h];
    float o[8][4];
    #pragma unroll
    for (int i = 0; i < 8; i++)
        #pragma unroll
        for (int j = 0; j < 4; j++) o[i][j] = 0.f;
    float m0 = -1e30f, m1 = -1e30f, l0 = 0.f, l1 = 0.f;

    for (int kt = 0; kt < 8; kt++) {
        const int st = kt & 1;
        CPA_WAIT0;
        __syncthreads();
        if (kt < 7) {
            size_t koff = bhk + (size_t)((kt+1)*128 + lrow)*QKVLD + lq*32;
            size_t voff = bhv + (size_t)((kt+1)*128 + lrow)*QKVLD + lq*32;
            #pragma unroll
            for (int i = 0; i < 4; i++) {
                cpa16(&KshS[st^1][lrow*KS_STRIDE + lq*16 + i*4], qh + koff + i*8);
                cpa16(&KslS[st^1][lrow*KS_STRIDE + lq*16 + i*4], ql + koff + i*8);
                cpa16(&VshS[st^1][lrow*KS_STRIDE + lq*16 + i*4], qh + voff + i*8);
                cpa16(&VslS[st^1][lrow*KS_STRIDE + lq*16 + i*4], ql + voff + i*8);
            }
        }
        CPA_COMMIT;

        const unsigned* Ksh = KshS[st]; const unsigned* Ksl = KslS[st];
        const unsigned* Vsh = VshS[st]; const unsigned* Vsl = VslS[st];
        const float* fmc = fmask + b*CN + kt*128;

        // ---- S = Q K^T (bf16x3, ldmatrix K in nt pairs) ----
        float s[16][4];
        #pragma unroll
        for (int nt = 0; nt < 16; nt++)
            #pragma unroll
            for (int i = 0; i < 4; i++) s[nt][i] = 0.f;
        #pragma unroll
        for (int ntp = 0; ntp < 8; ntp++) {
            float* sA = s[2*ntp];
            float* sB = s[2*ntp + 1];
            #pragma unroll
            for (int kw = 0; kw < 4; kw++) {
                unsigned kh[4], kl[4];
                ldsm4(kh, &Ksh[(ntp*16 + krow)*KS_STRIDE + kw*8 + kword]);
                ldsm4(kl, &Ksl[(ntp*16 + krow)*KS_STRIDE + kw*8 + kword]);
                mma16816(sA, qfh[kw], kh + 0);
                mma16816(sA, qfh[kw], kl + 0);
                mma16816(sA, qfl[kw], kh + 0);
                mma16816(sB, qfh[kw], kh + 2);
                mma16816(sB, qfh[kw], kl + 2);
                mma16816(sB, qfl[kw], kh + 2);
            }
        }

        // ---- scale + diag + col-mask, online softmax ----
        const int lr0 = wid*16 + qr, lr1 = lr0 + 8;
        float tmax0 = -3e38f, tmax1 = -3e38f;
        #pragma unroll
        for (int nt = 0; nt < 16; nt++) {
            int c0 = nt*8 + qk*2;
            float2 cmv = *(const float2*)(fmc + c0);
            float v0 = s[nt][0]*0.125f, v1 = s[nt][1]*0.125f;
            float v2 = s[nt][2]*0.125f, v3 = s[nt][3]*0.125f;
            if (qt == kt) {
                if (lr0 == c0)     v0 += wd;
                if (lr0 == c0 + 1) v1 += wd;
                if (lr1 == c0)     v2 += wd;
                if (lr1 == c0 + 1) v3 += wd;
            }
            if (cmv.x == 0.f) { v0 = -1e6f; v2 = -1e6f; }
            if (cmv.y == 0.f) { v1 = -1e6f; v3 = -1e6f; }
            s[nt][0] = v0; s[nt][1] = v1; s[nt][2] = v2; s[nt][3] = v3;
            tmax0 = fmaxf(tmax0, fmaxf(v0, v1));
            tmax1 = fmaxf(tmax1, fmaxf(v2, v3));
        }
        #pragma unroll
        for (int off = 1; off <= 2; off <<= 1) {
            tmax0 = fmaxf(tmax0, __shfl_xor_sync(0xffffffffu, tmax0, off));
            tmax1 = fmaxf(tmax1, __shfl_xor_sync(0xffffffffu, tmax1, off));
        }
        float mn0 = fmaxf(m0, tmax0), mn1 = fmaxf(m1, tmax1);
        float sc0 = __expf(m0 - mn0), sc1 = __expf(m1 - mn1);
        m0 = mn0; m1 = mn1;
        l0 *= sc0; l1 *= sc1;
        #pragma unroll
        for (int nt2 = 0; nt2 < 8; nt2++) {
            o[nt2][0] *= sc0; o[nt2][1] *= sc0;
            o[nt2][2] *= sc1; o[nt2][3] *= sc1;
        }
        float rs0 = 0.f, rs1 = 0.f;
        #pragma unroll
        for (int nt = 0; nt < 16; nt++) {
            float p0 = __expf(s[nt][0] - mn0);
            float p1 = __expf(s[nt][1] - mn0);
            float p2 = __expf(s[nt][2] - mn1);
            float p3 = __expf(s[nt][3] - mn1);
            rs0 += p0 + p1; rs1 += p2 + p3;
            s[nt][0] = p0; s[nt][1] = p1; s[nt][2] = p2; s[nt][3] = p3;
        }
        #pragma unroll
        for (int off = 1; off <= 2; off <<= 1) {
            rs0 += __shfl_xor_sync(0xffffffffu, rs0, off);
            rs1 += __shfl_xor_sync(0xffffffffu, rs1, off);
        }
        l0 += rs0; l1 += rs1;

        // ---- O += P V (bf16x3; V B-fragments via ldmatrix.trans) ----
        #pragma unroll
        for (int kk = 0; kk < 8; kk++) {
            const float* t0 = s[2*kk];
            const float* t1 = s[2*kk + 1];
            unsigned ah[4], al[4];
            {
                __nv_bfloat16 h00,l00,h01,l01,h02,l02,h03,l03;
                bsplit(t0[0],h00,l00); bsplit(t0[1],h01,l01);
                bsplit(t0[2],h02,l02); bsplit(t0[3],h03,l03);
                ah[0] = packbf(h00,h01); al[0] = packbf(l00,l01);
                ah[1] = packbf(h02,h03); al[1] = packbf(l02,l03);
                __nv_bfloat16 h10,l10,h11,l11,h12,l12,h13,l13;
                bsplit(t1[0],h10,l10); bsplit(t1[1],h11,l11);
                bsplit(t1[2],h12,l12); bsplit(t1[3],h13,l13);
                ah[2] = packbf(h10,h11); al[2] = packbf(l10,l11);
                ah[3] = packbf(h12,h13); al[3] = packbf(l12,l13);
            }
            #pragma unroll
            for (int ntp = 0; ntp < 4; ntp++) {
                unsigned vh[4], vl[4];
                ldsm4t(vh, &Vsh[(kk*16 + vrow)*KS_STRIDE + ntp*8 + vword]);
                ldsm4t(vl, &Vsl[(kk*16 + vrow)*KS_STRIDE + ntp*8 + vword]);
                mma16816(o[2*ntp],     ah, vh + 0);
                mma16816(o[2*ntp],     ah, vl + 0);
                mma16816(o[2*ntp],     al, vh + 0);
                mma16816(o[2*ntp + 1], ah, vh + 2);
                mma16816(o[2*ntp + 1], ah, vl + 2);
                mma16816(o[2*ntp + 1], al, vh + 2);
            }
        }
    }

    // ---- epilogue: normalize, fmask, split-store merged-head H ----
    const int grow0 = b*CN + qt*128 + wid*16 + qr;
    const int grow1 = grow0 + 8;
    float f0 = fmask[grow0] / l0;
    float f1 = fmask[grow1] / l1;
    #pragma unroll
    for (int nt2 = 0; nt2 < 8; nt2++) {
        int col = h*CHD + nt2*8 + qk*2;
        float v0 = o[nt2][0]*f0, v1 = o[nt2][1]*f0;
        float v2 = o[nt2][2]*f1, v3 = o[nt2][3]*f1;
        __nv_bfloat16 h0,lo0,h1,lo1,h2,lo2,h3,lo3;
        bsplit(v0,h0,lo0); bsplit(v1,h1,lo1);
        bsplit(v2,h2,lo2); bsplit(v3,h3,lo3);
        size_t i0 = (size_t)grow0*CO + col;
        size_t i1 = (size_t)grow1*CO + col;
        __nv_bfloat162 ph0; ph0.x=h0; ph0.y=h1;
        __nv_bfloat162 pl0; pl0.x=lo0; pl0.y=lo1;
        __nv_bfloat162 ph1; ph1.x=h2; ph1.y=h3;
        __nv_bfloat162 pl1; pl1.x=lo2; pl1.y=lo3;
        *(__nv_bfloat162*)(Hh + i0) = ph0;
        *(__nv_bfloat162*)(Hl + i0) = pl0;
        *(__nv_bfloat162*)(Hh + i1) = ph1;
        *(__nv_bfloat162*)(Hl + i1) = pl1;
    }
}

// ---------------------------------------------------------------------------
extern "C" void kernel_launch(void* const* d_in, const int* in_sizes, int n_in,
                              void* d_out, int out_size)
{
    const float* x = 0;  const unsigned char* mask_raw = 0;
    const float* slw = 0; const float* qkv_w = 0; const float* qkv_b = 0;
    const float* wbig[3] = {0,0,0}; const float* bsm[3] = {0,0,0};
    int nw = 0, nb = 0;

    for (int i = 0; i < n_in; i++) {
        switch (in_sizes[i]) {
            case 4194304: x        = (const float*)d_in[i]; break;
            case 8388608: /* adj unused */                  break;
            case 8192:    mask_raw = (const unsigned char*)d_in[i]; break;
            case 8:       slw      = (const float*)d_in[i]; break;
            case 786432:  qkv_w    = (const float*)d_in[i]; break;
            case 1536:    qkv_b    = (const float*)d_in[i]; break;
            case 262144:  if (nw < 3) wbig[nw++] = (const float*)d_in[i]; break;
            case 512:     if (nb < 3) bsm[nb++]  = (const float*)d_in[i]; break;
            default: break;
        }
    }
    const float *w1 = wbig[0], *w2 = wbig[1], *wr = wbig[2];
    const float *b1 = bsm[0],  *b2 = bsm[1],  *br = bsm[2];
    float* out = (float*)d_out;

    void *pf, *pxh, *pxl, *pqwh, *pqwl, *pw1h, *pw1l, *pw2h, *pw2l, *pwrh, *pwrl;
    void *pqh, *pql, *pHh, *pHl, *pTh, *pTl;
    cudaGetSymbolAddress(&pf,   g_fmask);
    cudaGetSymbolAddress(&pxh,  g_xh);   cudaGetSymbolAddress(&pxl,  g_xl);
    cudaGetSymbolAddress(&pqwh, g_qwh);  cudaGetSymbolAddress(&pqwl, g_qwl);
    cudaGetSymbolAddress(&pw1h, g_w1h);  cudaGetSymbolAddress(&pw1l, g_w1l);
    cudaGetSymbolAddress(&pw2h, g_w2h);  cudaGetSymbolAddress(&pw2l, g_w2l);
    cudaGetSymbolAddress(&pwrh, g_wrh);  cudaGetSymbolAddress(&pwrl, g_wrl);
    cudaGetSymbolAddress(&pqh,  g_qh);   cudaGetSymbolAddress(&pql,  g_ql);
    cudaGetSymbolAddress(&pHh,  g_Hh);   cudaGetSymbolAddress(&pHl,  g_Hl);
    cudaGetSymbolAddress(&pTh,  g_Th);   cudaGetSymbolAddress(&pTl,  g_Tl);

    float* fmp = (float*)pf;
    __nv_bfloat16 *xh=(__nv_bfloat16*)pxh, *xl=(__nv_bfloat16*)pxl;
    __nv_bfloat16 *qwh=(__nv_bfloat16*)pqwh, *qwl=(__nv_bfloat16*)pqwl;
    __nv_bfloat16 *w1h=(__nv_bfloat16*)pw1h, *w1l=(__nv_bfloat16*)pw1l;
    __nv_bfloat16 *w2h=(__nv_bfloat16*)pw2h, *w2l=(__nv_bfloat16*)pw2l;
    __nv_bfloat16 *wrh=(__nv_bfloat16*)pwrh, *wrl=(__nv_bfloat16*)pwrl;
    __nv_bfloat16 *qhp=(__nv_bfloat16*)pqh, *qlp=(__nv_bfloat16*)pql;
    __nv_bfloat16 *Hhp=(__nv_bfloat16*)pHh, *Hlp=(__nv_bfloat16*)pHl;
    __nv_bfloat16 *Thp=(__nv_bfloat16*)pTh, *Tlp=(__nv_bfloat16*)pTl;

    static int smem_set = 0;
    if (!smem_set) {
        cudaFuncSetAttribute(flash_tc, cudaFuncAttributeMaxDynamicSharedMemorySize,
                             FL_SMEM_BYTES);
        smem_set = 1;
    }

    // 0) mask convert + fused one-time splits
    mask_convert<<<1, 256>>>(mask_raw, fmp);
    split5<<<(SPLT+255)/256, 256>>>(x, qkv_w, w1, w2, wr,
                                    xh, xl, qwh, qwl, w1h, w1l, w2h, w2l, wrh, wrl);

    // 1) QKV = x @ qkv_w^T + qkv_b  -> split bf16
    gemm_tc<0><<<dim3(12, 64), 256>>>(xh, xl, qwh, qwl, qkv_b, fmp,
                                      (float*)0, qhp, qlp, CD, CD, CD, QKVLD);

    // 2-4) flash-fused attention -> split H (merged-head layout)
    flash_tc<<<dim3(CN/128, CB*CH), 256, FL_SMEM_BYTES>>>(qhp, qlp, slw, fmp, Hhp, Hlp);

    // 5) T = relu(H @ w1^T + b1) -> split bf16
    gemm_tc<1><<<dim3(4, 64), 256>>>(Hhp, Hlp, w1h, w1l, b1, fmp,
                                     (float*)0, Thp, Tlp, CO, CO, CO, CO);

    // 6) out = 0.5*(x @ wr^T + br)
    gemm_tc<2><<<dim3(4, 64), 256>>>(xh, xl, wrh, wrl, br, fmp,
                                     out, (__nv_bfloat16*)0, (__nv_bfloat16*)0, CD, CD, CD, CO);

    // 7) out += 0.5*fmask*(T @ w2^T + b2)
    gemm_tc<3><<<dim3(4, 64), 256>>>(Thp, Tlp, w2h, w2l, b2, fmp,
                                     out, (__nv_bfloat16*)0, (__nv_bfloat16*)0, CO, CO, CO, CO);
}

// round 10
// speedup vs baseline: 1.2006x; 1.2006x over previous
#include <cuda_runtime.h>
#include <cuda_bf16.h>
#include <math.h>

// Problem constants
#define CB 8
#define CN 1024
#define CD 512
#define CO 512
#define CH 8
#define CHD 64
#define QKVLD 1536   // 3*O
#define MROWS (CB*CN) // 8192

// ---------------- scratch (static device allocations; no cudaMalloc) ----------
__device__ float g_fmask[MROWS];
__device__ __nv_bfloat16 g_xh[MROWS*CD],  g_xl[MROWS*CD];
__device__ __nv_bfloat16 g_qwh[QKVLD*CD], g_qwl[QKVLD*CD];
__device__ __nv_bfloat16 g_w1h[CO*CO], g_w1l[CO*CO];
__device__ __nv_bfloat16 g_w2h[CO*CO], g_w2l[CO*CO];
__device__ __nv_bfloat16 g_wrh[CO*CD], g_wrl[CO*CD];
__device__ __nv_bfloat16 g_qh[(size_t)MROWS*QKVLD], g_ql[(size_t)MROWS*QKVLD];
__device__ __nv_bfloat16 g_Hh[MROWS*CO], g_Hl[MROWS*CO];
__device__ __nv_bfloat16 g_Th[MROWS*CO], g_Tl[MROWS*CO];

// ---------------------------------------------------------------------------
__device__ __forceinline__ void bsplit(float v, __nv_bfloat16& h, __nv_bfloat16& l){
    h = __float2bfloat16(v);
    l = __float2bfloat16(v - __bfloat162float(h));
}
__device__ __forceinline__ unsigned packbf(__nv_bfloat16 e, __nv_bfloat16 o){
    return ((unsigned)__bfloat16_as_ushort(o) << 16) | (unsigned)__bfloat16_as_ushort(e);
}
__device__ __forceinline__ void mma16816(float* c, const unsigned* a, const unsigned* b){
    asm volatile("mma.sync.aligned.m16n8k16.row.col.f32.bf16.bf16.f32 "
        "{%0,%1,%2,%3}, {%4,%5,%6,%7}, {%8,%9}, {%0,%1,%2,%3};"
        : "+f"(c[0]), "+f"(c[1]), "+f"(c[2]), "+f"(c[3])
        : "r"(a[0]), "r"(a[1]), "r"(a[2]), "r"(a[3]), "r"(b[0]), "r"(b[1]));
}
__device__ __forceinline__ void ldsm4(unsigned* r, const void* p){
    unsigned a = (unsigned)__cvta_generic_to_shared(p);
    asm volatile("ldmatrix.sync.aligned.m8n8.x4.shared.b16 {%0,%1,%2,%3}, [%4];"
        : "=r"(r[0]), "=r"(r[1]), "=r"(r[2]), "=r"(r[3]) : "r"(a));
}
__device__ __forceinline__ void ldsm4t(unsigned* r, const void* p){
    unsigned a = (unsigned)__cvta_generic_to_shared(p);
    asm volatile("ldmatrix.sync.aligned.m8n8.x4.trans.shared.b16 {%0,%1,%2,%3}, [%4];"
        : "=r"(r[0]), "=r"(r[1]), "=r"(r[2]), "=r"(r[3]) : "r"(a));
}
__device__ __forceinline__ void ldsm2(unsigned* r, const void* p){
    unsigned a = (unsigned)__cvta_generic_to_shared(p);
    asm volatile("ldmatrix.sync.aligned.m8n8.x2.shared.b16 {%0,%1}, [%2];"
        : "=r"(r[0]), "=r"(r[1]) : "r"(a));
}
__device__ __forceinline__ void cpa16(void* dst_smem, const void* src){
    unsigned sa = (unsigned)__cvta_generic_to_shared(dst_smem);
    asm volatile("cp.async.cg.shared.global [%0], [%1], 16;" :: "r"(sa), "l"(src));
}
#define CPA_COMMIT asm volatile("cp.async.commit_group;")
#define CPA_WAIT0  asm volatile("cp.async.wait_group 0;")

// ---------------------------------------------------------------------------
// Mask conversion (dtype auto-detect; bench data treated strictly as data)
// ---------------------------------------------------------------------------
__global__ void mask_convert(const unsigned char* __restrict__ raw,
                             float* __restrict__ fmask)
{
    __shared__ int s_m1, s_m23, s_gt1;
    int t = threadIdx.x;
    if (t == 0) { s_m1 = 0; s_m23 = 0; s_gt1 = 0; }
    __syncthreads();
    int m1 = 0, m23 = 0, g = 0;
    for (int i = t; i < MROWS; i += 256) {
        unsigned char v = raw[i];
        if (v) {
            int p = i & 3;
            if (p == 1) m1 = 1;
            if (p >= 2) m23 = 1;
            if (v > 1) g = 1;
        }
    }
    if (m1)  atomicOr(&s_m1, 1);
    if (m23) atomicOr(&s_m23, 1);
    if (g)   atomicOr(&s_gt1, 1);
    __syncthreads();
    int mis = s_m1 | s_m23;
    int mode;
    if (!mis)            mode = 0;
    else if (!s_gt1)     mode = 1;
    else if (s_m1)       mode = 3;
    else                 mode = 2;
    for (int i = t; i < MROWS; i += 256) {
        float f;
        if (mode == 0)      f = (((const int*)raw)[i]            != 0)   ? 1.f : 0.f;
        else if (mode == 1) f = (raw[i]                          != 0)   ? 1.f : 0.f;
        else if (mode == 2) f = (((const float*)raw)[i]          != 0.f) ? 1.f : 0.f;
        else                f = (((const unsigned short*)raw)[i] != 0)   ? 1.f : 0.f;
        fmask[i] = f;
    }
}

// ---------------------------------------------------------------------------
// Fused splitter: x, qkv_w, w1, w2, wr in one launch.
// ---------------------------------------------------------------------------
#define SPL0 (MROWS*CD)
#define SPL1 (QKVLD*CD)
#define SPL2 (CO*CO)
#define SPL3 (CO*CO)
#define SPL4 (CO*CD)
#define SPLT (SPL0+SPL1+SPL2+SPL3+SPL4)
__global__ void split5(
    const float* __restrict__ s0, const float* __restrict__ s1,
    const float* __restrict__ s2, const float* __restrict__ s3,
    const float* __restrict__ s4,
    __nv_bfloat16* __restrict__ h0, __nv_bfloat16* __restrict__ l0,
    __nv_bfloat16* __restrict__ h1, __nv_bfloat16* __restrict__ l1,
    __nv_bfloat16* __restrict__ h2, __nv_bfloat16* __restrict__ l2,
    __nv_bfloat16* __restrict__ h3, __nv_bfloat16* __restrict__ l3,
    __nv_bfloat16* __restrict__ h4, __nv_bfloat16* __restrict__ l4)
{
    int i = blockIdx.x * 256 + threadIdx.x;
    if (i >= SPLT) return;
    const float* s; __nv_bfloat16 *h, *l; int j = i;
    if (j < SPL0)                { s = s0; h = h0; l = l0; }
    else if ((j -= SPL0) < SPL1) { s = s1; h = h1; l = l1; }
    else if ((j -= SPL1) < SPL2) { s = s2; h = h2; l = l2; }
    else if ((j -= SPL2) < SPL3) { s = s3; h = h3; l = l3; }
    else { j -= SPL3;              s = s4; h = h4; l = l4; }
    __nv_bfloat16 hh, ll;
    bsplit(s[j], hh, ll);
    h[j] = hh; l[j] = ll;
}

// ---------------------------------------------------------------------------
// Tensor-core NT GEMM (bf16x3), cp.async double-buffered, ldmatrix fragments.
// 128x128, BK=16, 256 thr (8 warps = 2m x 4n).
// EPI: 0 split-store; 1 relu+split-store; 2 Cf=0.5v; 3 Cf+=0.5*fmask[m]*v
// ---------------------------------------------------------------------------
template<int EPI>
__global__ __launch_bounds__(256) void gemm_tc(
    const __nv_bfloat16* __restrict__ Ahg, const __nv_bfloat16* __restrict__ Alg,
    const __nv_bfloat16* __restrict__ Whg, const __nv_bfloat16* __restrict__ Wlg,
    const float* __restrict__ bias, const float* __restrict__ fmask,
    float* __restrict__ Cf, __nv_bfloat16* __restrict__ Ch, __nv_bfloat16* __restrict__ Cl,
    int K, int lda, int ldw, int ldc)
{
    __shared__ unsigned Ah[2][128*12], Al[2][128*12], Wh[2][128*12], Wl[2][128*12];
    const int tid = threadIdx.x;
    const int lane = tid & 31, wid = tid >> 5;
    const int wm = wid & 1, wn = wid >> 1;
    const int row0 = blockIdx.y * 128, col0 = blockIdx.x * 128;
    const int lr = tid >> 1, lh = tid & 1;
    const int qr = lane >> 2, qk = lane & 3;

    const int arow  = wm*64 + (lane & 7) + ((lane >> 3) & 1) * 8;
    const int aword = ((lane >> 4) & 1) * 4;
    const int brow  = wn*32 + (lane & 7);
    const int bword = ((lane >> 3) & 1) * 4;

    float acc[4][4][4];
    #pragma unroll
    for (int mt = 0; mt < 4; mt++)
        #pragma unroll
        for (int nt = 0; nt < 4; nt++)
            #pragma unroll
            for (int i = 0; i < 4; i++) acc[mt][nt][i] = 0.f;

    {
        size_t aoff = (size_t)(row0 + lr) * lda + lh * 8;
        size_t woff = (size_t)(col0 + lr) * ldw + lh * 8;
        cpa16(&Ah[0][lr*12 + lh*4], Ahg + aoff);
        cpa16(&Al[0][lr*12 + lh*4], Alg + aoff);
        cpa16(&Wh[0][lr*12 + lh*4], Whg + woff);
        cpa16(&Wl[0][lr*12 + lh*4], Wlg + woff);
    }
    CPA_COMMIT;

    int st = 0;
    for (int k0 = 0; k0 < K; k0 += 16, st ^= 1) {
        CPA_WAIT0;
        __syncthreads();
        if (k0 + 16 < K) {
            size_t aoff = (size_t)(row0 + lr) * lda + k0 + 16 + lh * 8;
            size_t woff = (size_t)(col0 + lr) * ldw + k0 + 16 + lh * 8;
            cpa16(&Ah[st^1][lr*12 + lh*4], Ahg + aoff);
            cpa16(&Al[st^1][lr*12 + lh*4], Alg + aoff);
            cpa16(&Wh[st^1][lr*12 + lh*4], Whg + woff);
            cpa16(&Wl[st^1][lr*12 + lh*4], Wlg + woff);
        }
        CPA_COMMIT;

        const unsigned* sAh = Ah[st]; const unsigned* sAl = Al[st];
        const unsigned* sWh = Wh[st]; const unsigned* sWl = Wl[st];
        unsigned afh[4][4], afl[4][4], bfh[4][2], bfl[4][2];
        #pragma unroll
        for (int mt = 0; mt < 4; mt++) {
            ldsm4(afh[mt], &sAh[(arow + mt*16)*12 + aword]);
            ldsm4(afl[mt], &sAl[(arow + mt*16)*12 + aword]);
        }
        #pragma unroll
        for (int nt = 0; nt < 4; nt++) {
            ldsm2(bfh[nt], &sWh[(brow + nt*8)*12 + bword]);
            ldsm2(bfl[nt], &sWl[(brow + nt*8)*12 + bword]);
        }
        #pragma unroll
        for (int mt = 0; mt < 4; mt++)
            #pragma unroll
            for (int nt = 0; nt < 4; nt++) {
                mma16816(acc[mt][nt], afh[mt], bfh[nt]);
                mma16816(acc[mt][nt], afh[mt], bfl[nt]);
                mma16816(acc[mt][nt], afl[mt], bfh[nt]);
            }
    }

    #pragma unroll
    for (int mt = 0; mt < 4; mt++)
        #pragma unroll
        for (int nt = 0; nt < 4; nt++) {
            const float* a = acc[mt][nt];
            int rbase = row0 + wm*64 + mt*16 + qr;
            int cbase = col0 + wn*32 + nt*8 + qk*2;
            float bv0 = bias[cbase], bv1 = bias[cbase + 1];
            #pragma unroll
            for (int hf = 0; hf < 2; hf++) {
                int r = rbase + hf*8;
                float v0 = a[hf*2+0] + bv0;
                float v1 = a[hf*2+1] + bv1;
                size_t idx = (size_t)r * ldc + cbase;
                if constexpr (EPI == 0 || EPI == 1) {
                    if constexpr (EPI == 1) { v0 = fmaxf(v0, 0.f); v1 = fmaxf(v1, 0.f); }
                    __nv_bfloat16 h0,l0,h1,l1;
                    bsplit(v0, h0, l0); bsplit(v1, h1, l1);
                    __nv_bfloat162 ph; ph.x = h0; ph.y = h1;
                    __nv_bfloat162 pl; pl.x = l0; pl.y = l1;
                    *(__nv_bfloat162*)(Ch + idx) = ph;
                    *(__nv_bfloat162*)(Cl + idx) = pl;
                } else if constexpr (EPI == 2) {
                    float2 o; o.x = 0.5f*v0; o.y = 0.5f*v1;
                    *(float2*)(Cf + idx) = o;
                } else {
                    float fm = 0.5f * fmask[r];
                    float2 cur = *(float2*)(Cf + idx);
                    cur.x += fm*v0; cur.y += fm*v1;
                    *(float2*)(Cf + idx) = cur;
                }
            }
        }
}

// ---------------------------------------------------------------------------
// Flash-fused attention (bf16x3, online softmax, P register-resident).
// R8 single-buffer skeleton; V stored ROW-MAJOR like K, P-V B-fragments via
// ldmatrix.x4.trans (no in-loop transpose pack).
// Grid: (CN/128, B*H). 256 thr = 8 warps x 16 Q rows.
// ---------------------------------------------------------------------------
#define KS_STRIDE 36
#define KS_WORDS (128*KS_STRIDE)
#define FL_SMEM_BYTES (4*KS_WORDS*4)   // K hi/lo + V hi/lo = 73728

__global__ void __launch_bounds__(256, 1) flash_tc(
    const __nv_bfloat16* __restrict__ qh, const __nv_bfloat16* __restrict__ ql,
    const float* __restrict__ slw, const float* __restrict__ fmask,
    __nv_bfloat16* __restrict__ Hh, __nv_bfloat16* __restrict__ Hl)
{
    extern __shared__ unsigned smem[];
    unsigned* Ksh = smem;
    unsigned* Ksl = smem + KS_WORDS;
    unsigned* Vsh = smem + 2*KS_WORDS;
    unsigned* Vsl = smem + 3*KS_WORDS;

    const int z = blockIdx.y, b = z >> 3, h = z & 7;
    const int qt = blockIdx.x;
    const int tid = threadIdx.x;
    const int lane = tid & 31, wid = tid >> 5;
    const int qr = lane >> 2, qk = lane & 3;

    const size_t bhq = (size_t)b*CN*QKVLD + h*CHD;
    const size_t bhk = bhq + CO;
    const size_t bhv = bhq + 2*CO;

    const int lrow = tid >> 1, lq = tid & 1;                // tile row loader
    const int krow  = ((lane >> 4) & 1) * 8 + (lane & 7);   // K ldsm row (+ntp*16)
    const int kword = ((lane >> 3) & 1) * 4;
    const int vrow  = lane & 15;                            // V ldsm.trans row (+kk*16)
    const int vword = (lane >> 4) * 4;                      // n 8-elem group

    // ---- stage Q tile through K buffer, pull fragments ----
    {
        size_t qoff = bhq + (size_t)(qt*128 + lrow)*QKVLD + lq*32;
        #pragma unroll
        for (int i = 0; i < 4; i++) {
            *(uint4*)&Ksh[lrow*KS_STRIDE + lq*16 + i*4] = *(const uint4*)(qh + qoff + i*8);
            *(uint4*)&Ksl[lrow*KS_STRIDE + lq*16 + i*4] = *(const uint4*)(ql + qoff + i*8);
        }
    }
    __syncthreads();
    unsigned qfh[4][4], qfl[4][4];
    #pragma unroll
    for (int kw = 0; kw < 4; kw++) {
        int r0 = (wid*16 + qr) * KS_STRIDE + kw*8;
        int r8 = (wid*16 + qr + 8) * KS_STRIDE + kw*8;
        qfh[kw][0] = Ksh[r0 + qk];     qfh[kw][1] = Ksh[r8 + qk];
        qfh[kw][2] = Ksh[r0 + qk + 4]; qfh[kw][3] = Ksh[r8 + qk + 4];
        qfl[kw][0] = Ksl[r0 + qk];     qfl[kw][1] = Ksl[r8 + qk];
        qfl[kw][2] = Ksl[r0 + qk + 4]; qfl[kw][3] = Ksl[r8 + qk + 4];
    }
    __syncthreads();

    const float wd = slw[h];
    float o[8][4];
    #pragma unroll
    for (int i = 0; i < 8; i++)
        #pragma unroll
        for (int j = 0; j < 4; j++) o[i][j] = 0.f;
    float m0 = -1e30f, m1 = -1e30f, l0 = 0.f, l1 = 0.f;

    for (int kt = 0; kt < 8; kt++) {
        // ---- load K tile + V tile (both plain row-major copies) ----
        {
            size_t koff = bhk + (size_t)(kt*128 + lrow)*QKVLD + lq*32;
            size_t voff = bhv + (size_t)(kt*128 + lrow)*QKVLD + lq*32;
            #pragma unroll
            for (int i = 0; i < 4; i++) {
                *(uint4*)&Ksh[lrow*KS_STRIDE + lq*16 + i*4] = *(const uint4*)(qh + koff + i*8);
                *(uint4*)&Ksl[lrow*KS_STRIDE + lq*16 + i*4] = *(const uint4*)(ql + koff + i*8);
                *(uint4*)&Vsh[lrow*KS_STRIDE + lq*16 + i*4] = *(const uint4*)(qh + voff + i*8);
                *(uint4*)&Vsl[lrow*KS_STRIDE + lq*16 + i*4] = *(const uint4*)(ql + voff + i*8);
            }
        }
        __syncthreads();

        const float* fmc = fmask + b*CN + kt*128;

        // ---- S = Q K^T (bf16x3, ldmatrix K in nt pairs) ----
        float s[16][4];
        #pragma unroll
        for (int nt = 0; nt < 16; nt++)
            #pragma unroll
            for (int i = 0; i < 4; i++) s[nt][i] = 0.f;
        #pragma unroll
        for (int ntp = 0; ntp < 8; ntp++) {
            float* sA = s[2*ntp];
            float* sB = s[2*ntp + 1];
            #pragma unroll
            for (int kw = 0; kw < 4; kw++) {
                unsigned kh[4], kl[4];
                ldsm4(kh, &Ksh[(ntp*16 + krow)*KS_STRIDE + kw*8 + kword]);
                ldsm4(kl, &Ksl[(ntp*16 + krow)*KS_STRIDE + kw*8 + kword]);
                mma16816(sA, qfh[kw], kh + 0);
                mma16816(sA, qfh[kw], kl + 0);
                mma16816(sA, qfl[kw], kh + 0);
                mma16816(sB, qfh[kw], kh + 2);
                mma16816(sB, qfh[kw], kl + 2);
                mma16816(sB, qfl[kw], kh + 2);
            }
        }

        // ---- scale + diag + col-mask, online softmax ----
        const int lr0 = wid*16 + qr, lr1 = lr0 + 8;
        float tmax0 = -3e38f, tmax1 = -3e38f;
        #pragma unroll
        for (int nt = 0; nt < 16; nt++) {
            int c0 = nt*8 + qk*2;
            float2 cmv = *(const float2*)(fmc + c0);
            float v0 = s[nt][0]*0.125f, v1 = s[nt][1]*0.125f;
            float v2 = s[nt][2]*0.125f, v3 = s[nt][3]*0.125f;
            if (qt == kt) {
                if (lr0 == c0)     v0 += wd;
                if (lr0 == c0 + 1) v1 += wd;
                if (lr1 == c0)     v2 += wd;
                if (lr1 == c0 + 1) v3 += wd;
            }
            if (cmv.x == 0.f) { v0 = -1e6f; v2 = -1e6f; }
            if (cmv.y == 0.f) { v1 = -1e6f; v3 = -1e6f; }
            s[nt][0] = v0; s[nt][1] = v1; s[nt][2] = v2; s[nt][3] = v3;
            tmax0 = fmaxf(tmax0, fmaxf(v0, v1));
            tmax1 = fmaxf(tmax1, fmaxf(v2, v3));
        }
        #pragma unroll
        for (int off = 1; off <= 2; off <<= 1) {
            tmax0 = fmaxf(tmax0, __shfl_xor_sync(0xffffffffu, tmax0, off));
            tmax1 = fmaxf(tmax1, __shfl_xor_sync(0xffffffffu, tmax1, off));
        }
        float mn0 = fmaxf(m0, tmax0), mn1 = fmaxf(m1, tmax1);
        float sc0 = __expf(m0 - mn0), sc1 = __expf(m1 - mn1);
        m0 = mn0; m1 = mn1;
        l0 *= sc0; l1 *= sc1;
        #pragma unroll
        for (int nt2 = 0; nt2 < 8; nt2++) {
            o[nt2][0] *= sc0; o[nt2][1] *= sc0;
            o[nt2][2] *= sc1; o[nt2][3] *= sc1;
        }
        float rs0 = 0.f, rs1 = 0.f;
        #pragma unroll
        for (int nt = 0; nt < 16; nt++) {
            float p0 = __expf(s[nt][0] - mn0);
            float p1 = __expf(s[nt][1] - mn0);
            float p2 = __expf(s[nt][2] - mn1);
            float p3 = __expf(s[nt][3] - mn1);
            rs0 += p0 + p1; rs1 += p2 + p3;
            s[nt][0] = p0; s[nt][1] = p1; s[nt][2] = p2; s[nt][3] = p3;
        }
        #pragma unroll
        for (int off = 1; off <= 2; off <<= 1) {
            rs0 += __shfl_xor_sync(0xffffffffu, rs0, off);
            rs1 += __shfl_xor_sync(0xffffffffu, rs1, off);
        }
        l0 += rs0; l1 += rs1;

        // ---- O += P V (bf16x3; V B-fragments via ldmatrix.trans) ----
        #pragma unroll
        for (int kk = 0; kk < 8; kk++) {
            const float* t0 = s[2*kk];
            const float* t1 = s[2*kk + 1];
            unsigned ah[4], al[4];
            {
                __nv_bfloat16 h00,l00,h01,l01,h02,l02,h03,l03;
                bsplit(t0[0],h00,l00); bsplit(t0[1],h01,l01);
                bsplit(t0[2],h02,l02); bsplit(t0[3],h03,l03);
                ah[0] = packbf(h00,h01); al[0] = packbf(l00,l01);
                ah[1] = packbf(h02,h03); al[1] = packbf(l02,l03);
                __nv_bfloat16 h10,l10,h11,l11,h12,l12,h13,l13;
                bsplit(t1[0],h10,l10); bsplit(t1[1],h11,l11);
                bsplit(t1[2],h12,l12); bsplit(t1[3],h13,l13);
                ah[2] = packbf(h10,h11); al[2] = packbf(l10,l11);
                ah[3] = packbf(h12,h13); al[3] = packbf(l12,l13);
            }
            #pragma unroll
            for (int ntp = 0; ntp < 4; ntp++) {
                unsigned vh[4], vl[4];
                ldsm4t(vh, &Vsh[(kk*16 + vrow)*KS_STRIDE + ntp*8 + vword]);
                ldsm4t(vl, &Vsl[(kk*16 + vrow)*KS_STRIDE + ntp*8 + vword]);
                mma16816(o[2*ntp],     ah, vh + 0);
                mma16816(o[2*ntp],     ah, vl + 0);
                mma16816(o[2*ntp],     al, vh + 0);
                mma16816(o[2*ntp + 1], ah, vh + 2);
                mma16816(o[2*ntp + 1], ah, vl + 2);
                mma16816(o[2*ntp + 1], al, vh + 2);
            }
        }
        __syncthreads();
    }

    // ---- epilogue: normalize, fmask, split-store merged-head H ----
    const int grow0 = b*CN + qt*128 + wid*16 + qr;
    const int grow1 = grow0 + 8;
    float f0 = fmask[grow0] / l0;
    float f1 = fmask[grow1] / l1;
    #pragma unroll
    for (int nt2 = 0; nt2 < 8; nt2++) {
        int col = h*CHD + nt2*8 + qk*2;
        float v0 = o[nt2][0]*f0, v1 = o[nt2][1]*f0;
        float v2 = o[nt2][2]*f1, v3 = o[nt2][3]*f1;
        __nv_bfloat16 h0,lo0,h1,lo1,h2,lo2,h3,lo3;
        bsplit(v0,h0,lo0); bsplit(v1,h1,lo1);
        bsplit(v2,h2,lo2); bsplit(v3,h3,lo3);
        size_t i0 = (size_t)grow0*CO + col;
        size_t i1 = (size_t)grow1*CO + col;
        __nv_bfloat162 ph0; ph0.x=h0; ph0.y=h1;
        __nv_bfloat162 pl0; pl0.x=lo0; pl0.y=lo1;
        __nv_bfloat162 ph1; ph1.x=h2; ph1.y=h3;
        __nv_bfloat162 pl1; pl1.x=lo2; pl1.y=lo3;
        *(__nv_bfloat162*)(Hh + i0) = ph0;
        *(__nv_bfloat162*)(Hl + i0) = pl0;
        *(__nv_bfloat162*)(Hh + i1) = ph1;
        *(__nv_bfloat162*)(Hl + i1) = pl1;
    }
}

// ---------------------------------------------------------------------------
extern "C" void kernel_launch(void* const* d_in, const int* in_sizes, int n_in,
                              void* d_out, int out_size)
{
    const float* x = 0;  const unsigned char* mask_raw = 0;
    const float* slw = 0; const float* qkv_w = 0; const float* qkv_b = 0;
    const float* wbig[3] = {0,0,0}; const float* bsm[3] = {0,0,0};
    int nw = 0, nb = 0;

    for (int i = 0; i < n_in; i++) {
        switch (in_sizes[i]) {
            case 4194304: x        = (const float*)d_in[i]; break;
            case 8388608: /* adj unused */                  break;
            case 8192:    mask_raw = (const unsigned char*)d_in[i]; break;
            case 8:       slw      = (const float*)d_in[i]; break;
            case 786432:  qkv_w    = (const float*)d_in[i]; break;
            case 1536:    qkv_b    = (const float*)d_in[i]; break;
            case 262144:  if (nw < 3) wbig[nw++] = (const float*)d_in[i]; break;
            case 512:     if (nb < 3) bsm[nb++]  = (const float*)d_in[i]; break;
            default: break;
        }
    }
    const float *w1 = wbig[0], *w2 = wbig[1], *wr = wbig[2];
    const float *b1 = bsm[0],  *b2 = bsm[1],  *br = bsm[2];
    float* out = (float*)d_out;

    void *pf, *pxh, *pxl, *pqwh, *pqwl, *pw1h, *pw1l, *pw2h, *pw2l, *pwrh, *pwrl;
    void *pqh, *pql, *pHh, *pHl, *pTh, *pTl;
    cudaGetSymbolAddress(&pf,   g_fmask);
    cudaGetSymbolAddress(&pxh,  g_xh);   cudaGetSymbolAddress(&pxl,  g_xl);
    cudaGetSymbolAddress(&pqwh, g_qwh);  cudaGetSymbolAddress(&pqwl, g_qwl);
    cudaGetSymbolAddress(&pw1h, g_w1h);  cudaGetSymbolAddress(&pw1l, g_w1l);
    cudaGetSymbolAddress(&pw2h, g_w2h);  cudaGetSymbolAddress(&pw2l, g_w2l);
    cudaGetSymbolAddress(&pwrh, g_wrh);  cudaGetSymbolAddress(&pwrl, g_wrl);
    cudaGetSymbolAddress(&pqh,  g_qh);   cudaGetSymbolAddress(&pql,  g_ql);
    cudaGetSymbolAddress(&pHh,  g_Hh);   cudaGetSymbolAddress(&pHl,  g_Hl);
    cudaGetSymbolAddress(&pTh,  g_Th);   cudaGetSymbolAddress(&pTl,  g_Tl);

    float* fmp = (float*)pf;
    __nv_bfloat16 *xh=(__nv_bfloat16*)pxh, *xl=(__nv_bfloat16*)pxl;
    __nv_bfloat16 *qwh=(__nv_bfloat16*)pqwh, *qwl=(__nv_bfloat16*)pqwl;
    __nv_bfloat16 *w1h=(__nv_bfloat16*)pw1h, *w1l=(__nv_bfloat16*)pw1l;
    __nv_bfloat16 *w2h=(__nv_bfloat16*)pw2h, *w2l=(__nv_bfloat16*)pw2l;
    __nv_bfloat16 *wrh=(__nv_bfloat16*)pwrh, *wrl=(__nv_bfloat16*)pwrl;
    __nv_bfloat16 *qhp=(__nv_bfloat16*)pqh, *qlp=(__nv_bfloat16*)pql;
    __nv_bfloat16 *Hhp=(__nv_bfloat16*)pHh, *Hlp=(__nv_bfloat16*)pHl;
    __nv_bfloat16 *Thp=(__nv_bfloat16*)pTh, *Tlp=(__nv_bfloat16*)pTl;

    static int smem_set = 0;
    if (!smem_set) {
        cudaFuncSetAttribute(flash_tc, cudaFuncAttributeMaxDynamicSharedMemorySize,
                             FL_SMEM_BYTES);
        smem_set = 1;
    }

    // 0) mask convert + fused one-time splits
    mask_convert<<<1, 256>>>(mask_raw, fmp);
    split5<<<(SPLT+255)/256, 256>>>(x, qkv_w, w1, w2, wr,
                                    xh, xl, qwh, qwl, w1h, w1l, w2h, w2l, wrh, wrl);

    // 1) QKV = x @ qkv_w^T + qkv_b  -> split bf16
    gemm_tc<0><<<dim3(12, 64), 256>>>(xh, xl, qwh, qwl, qkv_b, fmp,
                                      (float*)0, qhp, qlp, CD, CD, CD, QKVLD);

    // 2-4) flash-fused attention -> split H (merged-head layout)
    flash_tc<<<dim3(CN/128, CB*CH), 256, FL_SMEM_BYTES>>>(qhp, qlp, slw, fmp, Hhp, Hlp);

    // 5) T = relu(H @ w1^T + b1) -> split bf16
    gemm_tc<1><<<dim3(4, 64), 256>>>(Hhp, Hlp, w1h, w1l, b1, fmp,
                                     (float*)0, Thp, Tlp, CO, CO, CO, CO);

    // 6) out = 0.5*(x @ wr^T + br)
    gemm_tc<2><<<dim3(4, 64), 256>>>(xh, xl, wrh, wrl, br, fmp,
                                     out, (__nv_bfloat16*)0, (__nv_bfloat16*)0, CD, CD, CD, CO);

    // 7) out += 0.5*fmask*(T @ w2^T + b2)
    gemm_tc<3><<<dim3(4, 64), 256>>>(Thp, Tlp, w2h, w2l, b2, fmp,
                                     out, (__nv_bfloat16*)0, (__nv_bfloat16*)0, CO, CO, CO, CO);
}

// round 11
// speedup vs baseline: 1.3260x; 1.1044x over previous
#include <cuda_runtime.h>
#include <cuda_bf16.h>
#include <math.h>

// Problem constants
#define CB 8
#define CN 1024
#define CD 512
#define CO 512
#define CH 8
#define CHD 64
#define QKVLD 1536   // 3*O
#define MROWS (CB*CN) // 8192

// ---------------- scratch (static device allocations; no cudaMalloc) ----------
__device__ float g_fmask[MROWS];
__device__ __nv_bfloat16 g_xh[MROWS*CD],  g_xl[MROWS*CD];
__device__ __nv_bfloat16 g_qwh[QKVLD*CD], g_qwl[QKVLD*CD];
__device__ __nv_bfloat16 g_w1h[CO*CO], g_w1l[CO*CO];
__device__ __nv_bfloat16 g_w2h[CO*CO], g_w2l[CO*CO];
__device__ __nv_bfloat16 g_wrh[CO*CD], g_wrl[CO*CD];
__device__ __nv_bfloat16 g_qh[(size_t)MROWS*QKVLD], g_ql[(size_t)MROWS*QKVLD];
__device__ __nv_bfloat16 g_Hh[MROWS*CO], g_Hl[MROWS*CO];
__device__ __nv_bfloat16 g_Th[MROWS*CO], g_Tl[MROWS*CO];

// ---------------------------------------------------------------------------
__device__ __forceinline__ void bsplit(float v, __nv_bfloat16& h, __nv_bfloat16& l){
    h = __float2bfloat16(v);
    l = __float2bfloat16(v - __bfloat162float(h));
}
// Packed split: hi = bf16x2(v0 lo-half, v1 hi-half), lo = residuals, RN rounding
// (bit-identical to bsplit+pack, ~1/3 fewer instructions).
__device__ __forceinline__ unsigned pksplit(float v0, float v1, unsigned& lo){
    unsigned hi;
    asm("cvt.rn.bf16x2.f32 %0, %1, %2;" : "=r"(hi) : "f"(v1), "f"(v0));
    float h0 = __uint_as_float(hi << 16);
    float h1 = __uint_as_float(hi & 0xffff0000u);
    asm("cvt.rn.bf16x2.f32 %0, %1, %2;" : "=r"(lo) : "f"(v1 - h1), "f"(v0 - h0));
    return hi;
}
__device__ __forceinline__ void mma16816(float* c, const unsigned* a, const unsigned* b){
    asm volatile("mma.sync.aligned.m16n8k16.row.col.f32.bf16.bf16.f32 "
        "{%0,%1,%2,%3}, {%4,%5,%6,%7}, {%8,%9}, {%0,%1,%2,%3};"
        : "+f"(c[0]), "+f"(c[1]), "+f"(c[2]), "+f"(c[3])
        : "r"(a[0]), "r"(a[1]), "r"(a[2]), "r"(a[3]), "r"(b[0]), "r"(b[1]));
}
__device__ __forceinline__ void ldsm4(unsigned* r, const void* p){
    unsigned a = (unsigned)__cvta_generic_to_shared(p);
    asm volatile("ldmatrix.sync.aligned.m8n8.x4.shared.b16 {%0,%1,%2,%3}, [%4];"
        : "=r"(r[0]), "=r"(r[1]), "=r"(r[2]), "=r"(r[3]) : "r"(a));
}
__device__ __forceinline__ void ldsm4t(unsigned* r, const void* p){
    unsigned a = (unsigned)__cvta_generic_to_shared(p);
    asm volatile("ldmatrix.sync.aligned.m8n8.x4.trans.shared.b16 {%0,%1,%2,%3}, [%4];"
        : "=r"(r[0]), "=r"(r[1]), "=r"(r[2]), "=r"(r[3]) : "r"(a));
}
__device__ __forceinline__ void ldsm2(unsigned* r, const void* p){
    unsigned a = (unsigned)__cvta_generic_to_shared(p);
    asm volatile("ldmatrix.sync.aligned.m8n8.x2.shared.b16 {%0,%1}, [%2];"
        : "=r"(r[0]), "=r"(r[1]) : "r"(a));
}
__device__ __forceinline__ void cpa16(void* dst_smem, const void* src){
    unsigned sa = (unsigned)__cvta_generic_to_shared(dst_smem);
    asm volatile("cp.async.cg.shared.global [%0], [%1], 16;" :: "r"(sa), "l"(src));
}
#define CPA_COMMIT asm volatile("cp.async.commit_group;")
#define CPA_WAIT0  asm volatile("cp.async.wait_group 0;")

// ---------------------------------------------------------------------------
// Mask conversion (dtype auto-detect; bench data treated strictly as data)
// ---------------------------------------------------------------------------
__global__ void mask_convert(const unsigned char* __restrict__ raw,
                             float* __restrict__ fmask)
{
    __shared__ int s_m1, s_m23, s_gt1;
    int t = threadIdx.x;
    if (t == 0) { s_m1 = 0; s_m23 = 0; s_gt1 = 0; }
    __syncthreads();
    int m1 = 0, m23 = 0, g = 0;
    for (int i = t; i < MROWS; i += 256) {
        unsigned char v = raw[i];
        if (v) {
            int p = i & 3;
            if (p == 1) m1 = 1;
            if (p >= 2) m23 = 1;
            if (v > 1) g = 1;
        }
    }
    if (m1)  atomicOr(&s_m1, 1);
    if (m23) atomicOr(&s_m23, 1);
    if (g)   atomicOr(&s_gt1, 1);
    __syncthreads();
    int mis = s_m1 | s_m23;
    int mode;
    if (!mis)            mode = 0;
    else if (!s_gt1)     mode = 1;
    else if (s_m1)       mode = 3;
    else                 mode = 2;
    for (int i = t; i < MROWS; i += 256) {
        float f;
        if (mode == 0)      f = (((const int*)raw)[i]            != 0)   ? 1.f : 0.f;
        else if (mode == 1) f = (raw[i]                          != 0)   ? 1.f : 0.f;
        else if (mode == 2) f = (((const float*)raw)[i]          != 0.f) ? 1.f : 0.f;
        else                f = (((const unsigned short*)raw)[i] != 0)   ? 1.f : 0.f;
        fmask[i] = f;
    }
}

// ---------------------------------------------------------------------------
// Fused splitter: x, qkv_w, w1, w2, wr in one launch.
// ---------------------------------------------------------------------------
#define SPL0 (MROWS*CD)
#define SPL1 (QKVLD*CD)
#define SPL2 (CO*CO)
#define SPL3 (CO*CO)
#define SPL4 (CO*CD)
#define SPLT (SPL0+SPL1+SPL2+SPL3+SPL4)
__global__ void split5(
    const float* __restrict__ s0, const float* __restrict__ s1,
    const float* __restrict__ s2, const float* __restrict__ s3,
    const float* __restrict__ s4,
    __nv_bfloat16* __restrict__ h0, __nv_bfloat16* __restrict__ l0,
    __nv_bfloat16* __restrict__ h1, __nv_bfloat16* __restrict__ l1,
    __nv_bfloat16* __restrict__ h2, __nv_bfloat16* __restrict__ l2,
    __nv_bfloat16* __restrict__ h3, __nv_bfloat16* __restrict__ l3,
    __nv_bfloat16* __restrict__ h4, __nv_bfloat16* __restrict__ l4)
{
    int i = blockIdx.x * 256 + threadIdx.x;
    if (i >= SPLT) return;
    const float* s; __nv_bfloat16 *h, *l; int j = i;
    if (j < SPL0)                { s = s0; h = h0; l = l0; }
    else if ((j -= SPL0) < SPL1) { s = s1; h = h1; l = l1; }
    else if ((j -= SPL1) < SPL2) { s = s2; h = h2; l = l2; }
    else if ((j -= SPL2) < SPL3) { s = s3; h = h3; l = l3; }
    else { j -= SPL3;              s = s4; h = h4; l = l4; }
    __nv_bfloat16 hh, ll;
    bsplit(s[j], hh, ll);
    h[j] = hh; l[j] = ll;
}

// ---------------------------------------------------------------------------
// Tensor-core NT GEMM body (bf16x3), cp.async double-buffered, ldmatrix.
// Dynamic smem layout: Ah[2][1536] | Al | Wh | Wl  = 12288 u32 = 49152 B.
// 128x128 tile, BK=16, 256 thr (8 warps = 2m x 4n).
// EPI: 0 split-store; 1 relu+split-store; 2 Cf=0.5v; 3 Cf+=0.5*fmask[m]*v
// ---------------------------------------------------------------------------
template<int EPI>
__device__ __forceinline__ void gemm_body(
    unsigned* sm, int bx, int by,
    const __nv_bfloat16* __restrict__ Ahg, const __nv_bfloat16* __restrict__ Alg,
    const __nv_bfloat16* __restrict__ Whg, const __nv_bfloat16* __restrict__ Wlg,
    const float* __restrict__ bias, const float* __restrict__ fmask,
    float* __restrict__ Cf, __nv_bfloat16* __restrict__ Ch, __nv_bfloat16* __restrict__ Cl,
    int K, int lda, int ldw, int ldc)
{
    unsigned* Ah = sm;
    unsigned* Al = sm + 3072;
    unsigned* Wh = sm + 6144;
    unsigned* Wl = sm + 9216;
    const int tid = threadIdx.x;
    const int lane = tid & 31, wid = tid >> 5;
    const int wm = wid & 1, wn = wid >> 1;
    const int row0 = by * 128, col0 = bx * 128;
    const int lr = tid >> 1, lh = tid & 1;
    const int qr = lane >> 2, qk = lane & 3;

    const int arow  = wm*64 + (lane & 7) + ((lane >> 3) & 1) * 8;
    const int aword = ((lane >> 4) & 1) * 4;
    const int brow  = wn*32 + (lane & 7);
    const int bword = ((lane >> 3) & 1) * 4;

    float acc[4][4][4];
    #pragma unroll
    for (int mt = 0; mt < 4; mt++)
        #pragma unroll
        for (int nt = 0; nt < 4; nt++)
            #pragma unroll
            for (int i = 0; i < 4; i++) acc[mt][nt][i] = 0.f;

    {
        size_t aoff = (size_t)(row0 + lr) * lda + lh * 8;
        size_t woff = (size_t)(col0 + lr) * ldw + lh * 8;
        cpa16(&Ah[lr*12 + lh*4], Ahg + aoff);
        cpa16(&Al[lr*12 + lh*4], Alg + aoff);
        cpa16(&Wh[lr*12 + lh*4], Whg + woff);
        cpa16(&Wl[lr*12 + lh*4], Wlg + woff);
    }
    CPA_COMMIT;

    int st = 0;
    for (int k0 = 0; k0 < K; k0 += 16, st ^= 1) {
        CPA_WAIT0;
        __syncthreads();
        if (k0 + 16 < K) {
            int so = (st^1) * 1536;
            size_t aoff = (size_t)(row0 + lr) * lda + k0 + 16 + lh * 8;
            size_t woff = (size_t)(col0 + lr) * ldw + k0 + 16 + lh * 8;
            cpa16(&Ah[so + lr*12 + lh*4], Ahg + aoff);
            cpa16(&Al[so + lr*12 + lh*4], Alg + aoff);
            cpa16(&Wh[so + lr*12 + lh*4], Whg + woff);
            cpa16(&Wl[so + lr*12 + lh*4], Wlg + woff);
        }
        CPA_COMMIT;

        const int sc = st * 1536;
        const unsigned* sAh = Ah + sc; const unsigned* sAl = Al + sc;
        const unsigned* sWh = Wh + sc; const unsigned* sWl = Wl + sc;
        unsigned afh[4][4], afl[4][4], bfh[4][2], bfl[4][2];
        #pragma unroll
        for (int mt = 0; mt < 4; mt++) {
            ldsm4(afh[mt], &sAh[(arow + mt*16)*12 + aword]);
            ldsm4(afl[mt], &sAl[(arow + mt*16)*12 + aword]);
        }
        #pragma unroll
        for (int nt = 0; nt < 4; nt++) {
            ldsm2(bfh[nt], &sWh[(brow + nt*8)*12 + bword]);
            ldsm2(bfl[nt], &sWl[(brow + nt*8)*12 + bword]);
        }
        #pragma unroll
        for (int mt = 0; mt < 4; mt++)
            #pragma unroll
            for (int nt = 0; nt < 4; nt++) {
                mma16816(acc[mt][nt], afh[mt], bfh[nt]);
                mma16816(acc[mt][nt], afh[mt], bfl[nt]);
                mma16816(acc[mt][nt], afl[mt], bfh[nt]);
            }
    }

    #pragma unroll
    for (int mt = 0; mt < 4; mt++)
        #pragma unroll
        for (int nt = 0; nt < 4; nt++) {
            const float* a = acc[mt][nt];
            int rbase = row0 + wm*64 + mt*16 + qr;
            int cbase = col0 + wn*32 + nt*8 + qk*2;
            float bv0 = bias[cbase], bv1 = bias[cbase + 1];
            #pragma unroll
            for (int hf = 0; hf < 2; hf++) {
                int r = rbase + hf*8;
                float v0 = a[hf*2+0] + bv0;
                float v1 = a[hf*2+1] + bv1;
                size_t idx = (size_t)r * ldc + cbase;
                if constexpr (EPI == 0 || EPI == 1) {
                    if constexpr (EPI == 1) { v0 = fmaxf(v0, 0.f); v1 = fmaxf(v1, 0.f); }
                    unsigned pl, ph = pksplit(v0, v1, pl);
                    *(unsigned*)(Ch + idx) = ph;
                    *(unsigned*)(Cl + idx) = pl;
                } else if constexpr (EPI == 2) {
                    float2 o; o.x = 0.5f*v0; o.y = 0.5f*v1;
                    *(float2*)(Cf + idx) = o;
                } else {
                    float fm = 0.5f * fmask[r];
                    float2 cur = *(float2*)(Cf + idx);
                    cur.x += fm*v0; cur.y += fm*v1;
                    *(float2*)(Cf + idx) = cur;
                }
            }
        }
}

template<int EPI>
__global__ __launch_bounds__(256) void gemm_tc(
    const __nv_bfloat16* __restrict__ Ahg, const __nv_bfloat16* __restrict__ Alg,
    const __nv_bfloat16* __restrict__ Whg, const __nv_bfloat16* __restrict__ Wlg,
    const float* __restrict__ bias, const float* __restrict__ fmask,
    float* __restrict__ Cf, __nv_bfloat16* __restrict__ Ch, __nv_bfloat16* __restrict__ Cl,
    int K, int lda, int ldw, int ldc)
{
    extern __shared__ unsigned sm[];
    gemm_body<EPI>(sm, blockIdx.x, blockIdx.y, Ahg, Alg, Whg, Wlg, bias, fmask,
                   Cf, Ch, Cl, K, lda, ldw, ldc);
}
#define GEMM_SMEM 49152

// ---------------------------------------------------------------------------
// Fat kernel: flash attention (blocks [0,512)) + residual GEMM (blocks [512,768)).
// The residual tiles back-fill flash's tail waves — they depend only on split-x/wr.
// Flash: R10 structure (single buffer, V row-major, ldsm4t), pksplit P-pack.
// ---------------------------------------------------------------------------
#define KS_STRIDE 36
#define KS_WORDS (128*KS_STRIDE)
#define FL_SMEM_BYTES (4*KS_WORDS*4)   // 73728 (gemm branch uses 49152 of it)

__global__ void __launch_bounds__(256, 1) flash_fat(
    const __nv_bfloat16* __restrict__ qh, const __nv_bfloat16* __restrict__ ql,
    const float* __restrict__ slw, const float* __restrict__ fmask,
    __nv_bfloat16* __restrict__ Hh, __nv_bfloat16* __restrict__ Hl,
    const __nv_bfloat16* __restrict__ xh, const __nv_bfloat16* __restrict__ xl,
    const __nv_bfloat16* __restrict__ wrh, const __nv_bfloat16* __restrict__ wrl,
    const float* __restrict__ br, float* __restrict__ out)
{
    extern __shared__ unsigned smem[];
    const int bid = blockIdx.x;

    if (bid >= 512) {
        // residual GEMM tile: out = 0.5*(x @ wr^T + br)
        int idx = bid - 512;
        gemm_body<2>(smem, idx & 3, idx >> 2, xh, xl, wrh, wrl, br, fmask,
                     out, (__nv_bfloat16*)0, (__nv_bfloat16*)0, CD, CD, CD, CO);
        return;
    }

    unsigned* Ksh = smem;
    unsigned* Ksl = smem + KS_WORDS;
    unsigned* Vsh = smem + 2*KS_WORDS;
    unsigned* Vsl = smem + 3*KS_WORDS;

    const int qt = bid & 7, z = bid >> 3;
    const int b = z >> 3, h = z & 7;
    const int tid = threadIdx.x;
    const int lane = tid & 31, wid = tid >> 5;
    const int qr = lane >> 2, qk = lane & 3;

    const size_t bhq = (size_t)b*CN*QKVLD + h*CHD;
    const size_t bhk = bhq + CO;
    const size_t bhv = bhq + 2*CO;

    const int lrow = tid >> 1, lq = tid & 1;
    const int krow  = ((lane >> 4) & 1) * 8 + (lane & 7);
    const int kword = ((lane >> 3) & 1) * 4;
    const int vrow  = lane & 15;
    const int vword = (lane >> 4) * 4;

    // ---- stage Q tile through K buffer, pull fragments ----
    {
        size_t qoff = bhq + (size_t)(qt*128 + lrow)*QKVLD + lq*32;
        #pragma unroll
        for (int i = 0; i < 4; i++) {
            *(uint4*)&Ksh[lrow*KS_STRIDE + lq*16 + i*4] = *(const uint4*)(qh + qoff + i*8);
            *(uint4*)&Ksl[lrow*KS_STRIDE + lq*16 + i*4] = *(const uint4*)(ql + qoff + i*8);
        }
    }
    __syncthreads();
    unsigned qfh[4][4], qfl[4][4];
    #pragma unroll
    for (int kw = 0; kw < 4; kw++) {
        int r0 = (wid*16 + qr) * KS_STRIDE + kw*8;
        int r8 = (wid*16 + qr + 8) * KS_STRIDE + kw*8;
        qfh[kw][0] = Ksh[r0 + qk];     qfh[kw][1] = Ksh[r8 + qk];
        qfh[kw][2] = Ksh[r0 + qk + 4]; qfh[kw][3] = Ksh[r8 + qk + 4];
        qfl[kw][0] = Ksl[r0 + qk];     qfl[kw][1] = Ksl[r8 + qk];
        qfl[kw][2] = Ksl[r0 + qk + 4]; qfl[kw][3] = Ksl[r8 + qk + 4];
    }
    __syncthreads();

    const float wd = slw[h];
    float o[8][4];
    #pragma unroll
    for (int i = 0; i < 8; i++)
        #pragma unroll
        for (int j = 0; j < 4; j++) o[i][j] = 0.f;
    float m0 = -1e30f, m1 = -1e30f, l0 = 0.f, l1 = 0.f;

    for (int kt = 0; kt < 8; kt++) {
        {
            size_t koff = bhk + (size_t)(kt*128 + lrow)*QKVLD + lq*32;
            size_t voff = bhv + (size_t)(kt*128 + lrow)*QKVLD + lq*32;
            #pragma unroll
            for (int i = 0; i < 4; i++) {
                *(uint4*)&Ksh[lrow*KS_STRIDE + lq*16 + i*4] = *(const uint4*)(qh + koff + i*8);
                *(uint4*)&Ksl[lrow*KS_STRIDE + lq*16 + i*4] = *(const uint4*)(ql + koff + i*8);
                *(uint4*)&Vsh[lrow*KS_STRIDE + lq*16 + i*4] = *(const uint4*)(qh + voff + i*8);
                *(uint4*)&Vsl[lrow*KS_STRIDE + lq*16 + i*4] = *(const uint4*)(ql + voff + i*8);
            }
        }
        __syncthreads();

        const float* fmc = fmask + b*CN + kt*128;

        // ---- S = Q K^T (bf16x3, ldmatrix K in nt pairs) ----
        float s[16][4];
        #pragma unroll
        for (int nt = 0; nt < 16; nt++)
            #pragma unroll
            for (int i = 0; i < 4; i++) s[nt][i] = 0.f;
        #pragma unroll
        for (int ntp = 0; ntp < 8; ntp++) {
            float* sA = s[2*ntp];
            float* sB = s[2*ntp + 1];
            #pragma unroll
            for (int kw = 0; kw < 4; kw++) {
                unsigned kh[4], kl[4];
                ldsm4(kh, &Ksh[(ntp*16 + krow)*KS_STRIDE + kw*8 + kword]);
                ldsm4(kl, &Ksl[(ntp*16 + krow)*KS_STRIDE + kw*8 + kword]);
                mma16816(sA, qfh[kw], kh + 0);
                mma16816(sA, qfh[kw], kl + 0);
                mma16816(sA, qfl[kw], kh + 0);
                mma16816(sB, qfh[kw], kh + 2);
                mma16816(sB, qfh[kw], kl + 2);
                mma16816(sB, qfl[kw], kh + 2);
            }
        }

        // ---- scale + diag + col-mask, online softmax ----
        const int lr0 = wid*16 + qr, lr1 = lr0 + 8;
        float tmax0 = -3e38f, tmax1 = -3e38f;
        #pragma unroll
        for (int nt = 0; nt < 16; nt++) {
            int c0 = nt*8 + qk*2;
            float2 cmv = *(const float2*)(fmc + c0);
            float v0 = s[nt][0]*0.125f, v1 = s[nt][1]*0.125f;
            float v2 = s[nt][2]*0.125f, v3 = s[nt][3]*0.125f;
            if (qt == kt) {
                if (lr0 == c0)     v0 += wd;
                if (lr0 == c0 + 1) v1 += wd;
                if (lr1 == c0)     v2 += wd;
                if (lr1 == c0 + 1) v3 += wd;
            }
            if (cmv.x == 0.f) { v0 = -1e6f; v2 = -1e6f; }
            if (cmv.y == 0.f) { v1 = -1e6f; v3 = -1e6f; }
            s[nt][0] = v0; s[nt][1] = v1; s[nt][2] = v2; s[nt][3] = v3;
            tmax0 = fmaxf(tmax0, fmaxf(v0, v1));
            tmax1 = fmaxf(tmax1, fmaxf(v2, v3));
        }
        #pragma unroll
        for (int off = 1; off <= 2; off <<= 1) {
            tmax0 = fmaxf(tmax0, __shfl_xor_sync(0xffffffffu, tmax0, off));
            tmax1 = fmaxf(tmax1, __shfl_xor_sync(0xffffffffu, tmax1, off));
        }
        float mn0 = fmaxf(m0, tmax0), mn1 = fmaxf(m1, tmax1);
        float sc0 = __expf(m0 - mn0), sc1 = __expf(m1 - mn1);
        m0 = mn0; m1 = mn1;
        l0 *= sc0; l1 *= sc1;
        #pragma unroll
        for (int nt2 = 0; nt2 < 8; nt2++) {
            o[nt2][0] *= sc0; o[nt2][1] *= sc0;
            o[nt2][2] *= sc1; o[nt2][3] *= sc1;
        }
        float rs0 = 0.f, rs1 = 0.f;
        #pragma unroll
        for (int nt = 0; nt < 16; nt++) {
            float p0 = __expf(s[nt][0] - mn0);
            float p1 = __expf(s[nt][1] - mn0);
            float p2 = __expf(s[nt][2] - mn1);
            float p3 = __expf(s[nt][3] - mn1);
            rs0 += p0 + p1; rs1 += p2 + p3;
            s[nt][0] = p0; s[nt][1] = p1; s[nt][2] = p2; s[nt][3] = p3;
        }
        #pragma unroll
        for (int off = 1; off <= 2; off <<= 1) {
            rs0 += __shfl_xor_sync(0xffffffffu, rs0, off);
            rs1 += __shfl_xor_sync(0xffffffffu, rs1, off);
        }
        l0 += rs0; l1 += rs1;

        // ---- O += P V (bf16x3; pksplit P pack; ldmatrix.trans V) ----
        #pragma unroll
        for (int kk = 0; kk < 8; kk++) {
            const float* t0 = s[2*kk];
            const float* t1 = s[2*kk + 1];
            unsigned ah[4], al[4];
            ah[0] = pksplit(t0[0], t0[1], al[0]);
            ah[1] = pksplit(t0[2], t0[3], al[1]);
            ah[2] = pksplit(t1[0], t1[1], al[2]);
            ah[3] = pksplit(t1[2], t1[3], al[3]);
            #pragma unroll
            for (int ntp = 0; ntp < 4; ntp++) {
                unsigned vh[4], vl[4];
                ldsm4t(vh, &Vsh[(kk*16 + vrow)*KS_STRIDE + ntp*8 + vword]);
                ldsm4t(vl, &Vsl[(kk*16 + vrow)*KS_STRIDE + ntp*8 + vword]);
                mma16816(o[2*ntp],     ah, vh + 0);
                mma16816(o[2*ntp],     ah, vl + 0);
                mma16816(o[2*ntp],     al, vh + 0);
                mma16816(o[2*ntp + 1], ah, vh + 2);
                mma16816(o[2*ntp + 1], ah, vl + 2);
                mma16816(o[2*ntp + 1], al, vh + 2);
            }
        }
        __syncthreads();
    }

    // ---- epilogue: normalize, fmask, split-store merged-head H ----
    const int grow0 = b*CN + qt*128 + wid*16 + qr;
    const int grow1 = grow0 + 8;
    float f0 = fmask[grow0] / l0;
    float f1 = fmask[grow1] / l1;
    #pragma unroll
    for (int nt2 = 0; nt2 < 8; nt2++) {
        int col = h*CHD + nt2*8 + qk*2;
        size_t i0 = (size_t)grow0*CO + col;
        size_t i1 = (size_t)grow1*CO + col;
        unsigned pl0, ph0 = pksplit(o[nt2][0]*f0, o[nt2][1]*f0, pl0);
        unsigned pl1, ph1 = pksplit(o[nt2][2]*f1, o[nt2][3]*f1, pl1);
        *(unsigned*)(Hh + i0) = ph0;
        *(unsigned*)(Hl + i0) = pl0;
        *(unsigned*)(Hh + i1) = ph1;
        *(unsigned*)(Hl + i1) = pl1;
    }
}

// ---------------------------------------------------------------------------
extern "C" void kernel_launch(void* const* d_in, const int* in_sizes, int n_in,
                              void* d_out, int out_size)
{
    const float* x = 0;  const unsigned char* mask_raw = 0;
    const float* slw = 0; const float* qkv_w = 0; const float* qkv_b = 0;
    const float* wbig[3] = {0,0,0}; const float* bsm[3] = {0,0,0};
    int nw = 0, nb = 0;

    for (int i = 0; i < n_in; i++) {
        switch (in_sizes[i]) {
            case 4194304: x        = (const float*)d_in[i]; break;
            case 8388608: /* adj unused */                  break;
            case 8192:    mask_raw = (const unsigned char*)d_in[i]; break;
            case 8:       slw      = (const float*)d_in[i]; break;
            case 786432:  qkv_w    = (const float*)d_in[i]; break;
            case 1536:    qkv_b    = (const float*)d_in[i]; break;
            case 262144:  if (nw < 3) wbig[nw++] = (const float*)d_in[i]; break;
            case 512:     if (nb < 3) bsm[nb++]  = (const float*)d_in[i]; break;
            default: break;
        }
    }
    const float *w1 = wbig[0], *w2 = wbig[1], *wr = wbig[2];
    const float *b1 = bsm[0],  *b2 = bsm[1],  *br = bsm[2];
    float* out = (float*)d_out;

    void *pf, *pxh, *pxl, *pqwh, *pqwl, *pw1h, *pw1l, *pw2h, *pw2l, *pwrh, *pwrl;
    void *pqh, *pql, *pHh, *pHl, *pTh, *pTl;
    cudaGetSymbolAddress(&pf,   g_fmask);
    cudaGetSymbolAddress(&pxh,  g_xh);   cudaGetSymbolAddress(&pxl,  g_xl);
    cudaGetSymbolAddress(&pqwh, g_qwh);  cudaGetSymbolAddress(&pqwl, g_qwl);
    cudaGetSymbolAddress(&pw1h, g_w1h);  cudaGetSymbolAddress(&pw1l, g_w1l);
    cudaGetSymbolAddress(&pw2h, g_w2h);  cudaGetSymbolAddress(&pw2l, g_w2l);
    cudaGetSymbolAddress(&pwrh, g_wrh);  cudaGetSymbolAddress(&pwrl, g_wrl);
    cudaGetSymbolAddress(&pqh,  g_qh);   cudaGetSymbolAddress(&pql,  g_ql);
    cudaGetSymbolAddress(&pHh,  g_Hh);   cudaGetSymbolAddress(&pHl,  g_Hl);
    cudaGetSymbolAddress(&pTh,  g_Th);   cudaGetSymbolAddress(&pTl,  g_Tl);

    float* fmp = (float*)pf;
    __nv_bfloat16 *xh=(__nv_bfloat16*)pxh, *xl=(__nv_bfloat16*)pxl;
    __nv_bfloat16 *qwh=(__nv_bfloat16*)pqwh, *qwl=(__nv_bfloat16*)pqwl;
    __nv_bfloat16 *w1h=(__nv_bfloat16*)pw1h, *w1l=(__nv_bfloat16*)pw1l;
    __nv_bfloat16 *w2h=(__nv_bfloat16*)pw2h, *w2l=(__nv_bfloat16*)pw2l;
    __nv_bfloat16 *wrh=(__nv_bfloat16*)pwrh, *wrl=(__nv_bfloat16*)pwrl;
    __nv_bfloat16 *qhp=(__nv_bfloat16*)pqh, *qlp=(__nv_bfloat16*)pql;
    __nv_bfloat16 *Hhp=(__nv_bfloat16*)pHh, *Hlp=(__nv_bfloat16*)pHl;
    __nv_bfloat16 *Thp=(__nv_bfloat16*)pTh, *Tlp=(__nv_bfloat16*)pTl;

    static int smem_set = 0;
    if (!smem_set) {
        cudaFuncSetAttribute(flash_fat, cudaFuncAttributeMaxDynamicSharedMemorySize,
                             FL_SMEM_BYTES);
        smem_set = 1;
    }

    // 0) mask convert + fused one-time splits
    mask_convert<<<1, 256>>>(mask_raw, fmp);
    split5<<<(SPLT+255)/256, 256>>>(x, qkv_w, w1, w2, wr,
                                    xh, xl, qwh, qwl, w1h, w1l, w2h, w2l, wrh, wrl);

    // 1) QKV = x @ qkv_w^T + qkv_b  -> split bf16
    gemm_tc<0><<<dim3(12, 64), 256, GEMM_SMEM>>>(xh, xl, qwh, qwl, qkv_b, fmp,
                                      (float*)0, qhp, qlp, CD, CD, CD, QKVLD);

    // 2-4) flash attention + residual gemm (tail-filled) in one launch
    flash_fat<<<768, 256, FL_SMEM_BYTES>>>(qhp, qlp, slw, fmp, Hhp, Hlp,
                                           xh, xl, wrh, wrl, br, out);

    // 5) T = relu(H @ w1^T + b1) -> split bf16
    gemm_tc<1><<<dim3(4, 64), 256, GEMM_SMEM>>>(Hhp, Hlp, w1h, w1l, b1, fmp,
                                     (float*)0, Thp, Tlp, CO, CO, CO, CO);

    // 6) out += 0.5*fmask*(T @ w2^T + b2)   (out initialized by fat kernel)
    gemm_tc<3><<<dim3(4, 64), 256, GEMM_SMEM>>>(Thp, Tlp, w2h, w2l, b2, fmp,
                                     out, (__nv_bfloat16*)0, (__nv_bfloat16*)0, CO, CO, CO, CO);
}